// round 3
// baseline (speedup 1.0000x reference)
#include <cuda_runtime.h>
#include <math.h>

#define N_NODES 100000
#define N_EDGES 1600000
#define DIM     128
#define N_ROOTS 1024
#define TAU_INV 10.0f
#define EPS     1e-10f
#define NEG     0.2f

// ---------------- scratch (device globals; no allocations allowed) ----------
__device__ __align__(16) float g_h  [N_NODES * DIM];   // h = xW + b
__device__ __align__(16) float g_x1 [N_NODES * DIM];   // hop-0 output
__device__ __align__(16) float g_acc[N_NODES * DIM];   // scatter accumulator
__device__ float    g_s  [N_NODES];
__device__ float    g_t  [N_NODES];
__device__ float    g_z  [N_NODES];
__device__ unsigned g_m  [N_NODES];         // ordered-int encoded segment max
__device__ float    g_logit[N_EDGES];       // (s+t+g)/tau, cached between passes
__device__ int      g_src[N_EDGES];
__device__ int      g_dst[N_EDGES];
__device__ int      g_root[N_ROOTS];
__device__ int      g_is64;                 // 1 if indices are int64 in memory

// order-preserving float<->uint encoding for atomicMax on floats
__device__ __forceinline__ unsigned fkey(float f) {
    unsigned u = __float_as_uint(f);
    return (u & 0x80000000u) ? ~u : (u | 0x80000000u);
}
__device__ __forceinline__ float fkey_inv(unsigned k) {
    return (k & 0x80000000u) ? __uint_as_float(k ^ 0x80000000u)
                             : __uint_as_float(~k);
}

// ---------------- kernels ---------------------------------------------------

// Detect index dtype: int64 little-endian has high word == 0 for every value
// (indices are in [0, 100000)). For int32 data the "high words" are random
// indices — all-zero over 128 samples is impossible in practice.
__global__ void k_detect(const int* __restrict__ ei_raw) {
    int all0 = 1;
    for (int i = 0; i < 128; i++)
        if (ei_raw[2 * i + 1] != 0) { all0 = 0; break; }
    g_is64 = all0;
}

__global__ void k_convert(const void* __restrict__ ei_raw,
                          const void* __restrict__ roots_raw) {
    int i = blockIdx.x * blockDim.x + threadIdx.x;
    int is64 = g_is64;
    if (i < N_EDGES) {
        if (is64) {
            const long long* e = (const long long*)ei_raw;
            g_src[i] = (int)e[i];
            g_dst[i] = (int)e[N_EDGES + i];
        } else {
            const int* e = (const int*)ei_raw;
            g_src[i] = e[i];
            g_dst[i] = e[N_EDGES + i];
        }
    }
    if (i < N_ROOTS) {
        g_root[i] = is64 ? (int)((const long long*)roots_raw)[i]
                         : ((const int*)roots_raw)[i];
    }
}

__global__ void k_init() {
    int i = blockIdx.x * blockDim.x + threadIdx.x;
    if (i < N_NODES * (DIM / 4))
        ((float4*)g_acc)[i] = make_float4(0.f, 0.f, 0.f, 0.f);
    if (i < N_NODES) { g_z[i] = 0.f; g_m[i] = 0u; }
}

// h = x @ W + b ; s = lrelu(h.att_src) ; t = lrelu(h.att_dst)
// one warp per row; W (64 KB) stays hot in L1/L2
__global__ void k_gemm(const float* __restrict__ x_ext, int use_x1,
                       const float* __restrict__ W,  const float* __restrict__ b,
                       const float* __restrict__ as_, const float* __restrict__ ad_) {
    int row  = (blockIdx.x * blockDim.x + threadIdx.x) >> 5;
    int lane = threadIdx.x & 31;
    if (row >= N_NODES) return;
    const unsigned FULL = 0xffffffffu;

    const float4* x4 = (const float4*)(use_x1 ? g_x1 : x_ext);
    const float4* W4 = (const float4*)W;
    float4 xr  = x4[row * 32 + lane];              // lane holds x[row][4*lane..+3]
    float4 acc = ((const float4*)b)[lane];         // cols 4*lane..4*lane+3

    #pragma unroll 8
    for (int kk = 0; kk < 32; kk++) {
        float xk0 = __shfl_sync(FULL, xr.x, kk);   // x[row][4kk+0]
        float xk1 = __shfl_sync(FULL, xr.y, kk);
        float xk2 = __shfl_sync(FULL, xr.z, kk);
        float xk3 = __shfl_sync(FULL, xr.w, kk);
        float4 w0 = W4[(4 * kk + 0) * 32 + lane];
        float4 w1 = W4[(4 * kk + 1) * 32 + lane];
        float4 w2 = W4[(4 * kk + 2) * 32 + lane];
        float4 w3 = W4[(4 * kk + 3) * 32 + lane];
        acc.x += xk0 * w0.x; acc.y += xk0 * w0.y; acc.z += xk0 * w0.z; acc.w += xk0 * w0.w;
        acc.x += xk1 * w1.x; acc.y += xk1 * w1.y; acc.z += xk1 * w1.z; acc.w += xk1 * w1.w;
        acc.x += xk2 * w2.x; acc.y += xk2 * w2.y; acc.z += xk2 * w2.z; acc.w += xk2 * w2.w;
        acc.x += xk3 * w3.x; acc.y += xk3 * w3.y; acc.z += xk3 * w3.z; acc.w += xk3 * w3.w;
    }

    ((float4*)g_h)[row * 32 + lane] = acc;

    float4 a4 = ((const float4*)as_)[lane];
    float4 d4 = ((const float4*)ad_)[lane];
    float sp = acc.x * a4.x + acc.y * a4.y + acc.z * a4.z + acc.w * a4.w;
    float tp = acc.x * d4.x + acc.y * d4.y + acc.z * d4.z + acc.w * d4.w;
    #pragma unroll
    for (int o = 16; o; o >>= 1) {
        sp += __shfl_xor_sync(FULL, sp, o);
        tp += __shfl_xor_sync(FULL, tp, o);
    }
    if (lane == 0) {
        g_s[row] = sp > 0.f ? sp : NEG * sp;
        g_t[row] = tp > 0.f ? tp : NEG * tp;
    }
}

// per-edge scaled logit + segment max (atomicMax on encoded float)
__global__ void k_edge(const float* __restrict__ gu) {
    int i = blockIdx.x * blockDim.x + threadIdx.x;
    if (i >= N_EDGES) return;
    int s = g_src[i], d = g_dst[i];
    float u = gu[i];
    float g = -logf(-logf(u + EPS) + EPS);          // Gumbel(0,1)
    float l = (g_s[s] + g_t[d] + g) * TAU_INV;
    g_logit[i] = l;
    atomicMax(&g_m[d], fkey(l));
}

// one warp per edge: e = exp(l - m[dst]); z[dst] += e; acc[dst] += e * h[src]
__global__ void k_scatter() {
    int t = blockIdx.x * blockDim.x + threadIdx.x;
    int e = t >> 5;
    if (e >= N_EDGES) return;
    int lane = threadIdx.x & 31;
    const unsigned FULL = 0xffffffffu;

    int s = 0, d = 0; float w = 0.f;
    if (lane == 0) {
        s = g_src[e]; d = g_dst[e];
        float m = fkey_inv(g_m[d]);
        w = expf(g_logit[e] - m);
        atomicAdd(&g_z[d], w);
    }
    s = __shfl_sync(FULL, s, 0);
    d = __shfl_sync(FULL, d, 0);
    w = __shfl_sync(FULL, w, 0);

    float4 hv = ((const float4*)g_h)[s * 32 + lane];
    float* p = &g_acc[d * DIM + lane * 4];
    asm volatile("red.global.add.v4.f32 [%0], {%1,%2,%3,%4};"
                 :: "l"(p), "f"(w * hv.x), "f"(w * hv.y),
                    "f"(w * hv.z), "f"(w * hv.w) : "memory");
}

// hop-0 epilogue over all nodes: x1 = relu(acc/(z+eps) + x_in)
__global__ void k_finish(const float* __restrict__ x_ext) {
    int i = blockIdx.x * blockDim.x + threadIdx.x;
    if (i >= N_NODES * (DIM / 4)) return;
    int node = i >> 5;
    float inv = 1.f / (g_z[node] + EPS);
    float4 a = ((const float4*)g_acc)[i];
    float4 x = ((const float4*)x_ext)[i];
    float4 r;
    r.x = fmaxf(a.x * inv + x.x, 0.f);
    r.y = fmaxf(a.y * inv + x.y, 0.f);
    r.z = fmaxf(a.z * inv + x.z, 0.f);
    r.w = fmaxf(a.w * inv + x.w, 0.f);
    ((float4*)g_x1)[i] = r;
}

// hop-1 epilogue only at the 1024 roots, straight to d_out
__global__ void k_final(float* __restrict__ out) {
    int i = blockIdx.x * blockDim.x + threadIdx.x;
    if (i >= N_ROOTS * (DIM / 4)) return;
    int r = i >> 5, lane = i & 31;
    int node = g_root[r];
    float inv = 1.f / (g_z[node] + EPS);
    float4 a = ((const float4*)g_acc)[node * 32 + lane];
    float4 x = ((const float4*)g_x1)[node * 32 + lane];
    float4 o;
    o.x = fmaxf(a.x * inv + x.x, 0.f);
    o.y = fmaxf(a.y * inv + x.y, 0.f);
    o.z = fmaxf(a.z * inv + x.z, 0.f);
    o.w = fmaxf(a.w * inv + x.w, 0.f);
    ((float4*)out)[i] = o;
}

// ---------------- launch -----------------------------------------------------

extern "C" void kernel_launch(void* const* d_in, const int* in_sizes, int n_in,
                              void* d_out, int out_size) {
    const float* x     = (const float*)d_in[0];
    const void*  ei    = d_in[1];
    const void*  roots = d_in[2];
    const float* gu    = (const float*)d_in[3];
    const float* W     = (const float*)d_in[4];
    const float* b     = (const float*)d_in[5];
    const float* as_   = (const float*)d_in[6];
    const float* ad_   = (const float*)d_in[7];
    float*       out   = (float*)d_out;

    const int TB = 256;
    k_detect<<<1, 1>>>((const int*)ei);
    k_convert<<<(N_EDGES + TB - 1) / TB, TB>>>(ei, roots);

    for (int hop = 0; hop < 2; hop++) {
        k_init<<<(N_NODES * 32 + TB - 1) / TB, TB>>>();
        k_gemm<<<(N_NODES * 32 + TB - 1) / TB, TB>>>(x, hop, W, b, as_, ad_);
        k_edge<<<(N_EDGES + TB - 1) / TB, TB>>>(gu + (size_t)hop * N_EDGES);
        k_scatter<<<(N_EDGES * 32 + TB - 1) / TB, TB>>>();
        if (hop == 0) k_finish<<<(N_NODES * 32 + TB - 1) / TB, TB>>>(x);
        else          k_final<<<(N_ROOTS * 32 + TB - 1) / TB, TB>>>(out);
    }
}

// round 5
// speedup vs baseline: 1.2640x; 1.2640x over previous
#include <cuda_runtime.h>
#include <math.h>

#define N_NODES 100000
#define N_EDGES 1600000
#define DIM     128
#define N_ROOTS 1024
#define TAU_INV 10.0f
#define EPS     1e-10f
#define NEG     0.2f

#define ROWS_PER_BLOCK 64
#define ROWS_PER_WARP  8

// ---------------- scratch (device globals; no allocations allowed) ----------
__device__ __align__(16) float g_h  [N_NODES * DIM];   // h = xW + b
__device__ __align__(16) float g_x1 [N_NODES * DIM];   // hop-0 output
__device__ __align__(16) float g_acc[N_NODES * DIM];   // scatter accumulator
__device__ float    g_s  [N_NODES];
__device__ float    g_t  [N_NODES];
__device__ float    g_z  [N_NODES];
__device__ unsigned g_m  [N_NODES];         // ordered-int encoded segment max
__device__ float    g_logit[N_EDGES];
__device__ int      g_src[N_EDGES];
__device__ int      g_dst[N_EDGES];
__device__ int      g_root[N_ROOTS];
__device__ int      g_is64;                 // 1 if indices are int64 in memory

// order-preserving float<->uint encoding for atomicMax on floats
__device__ __forceinline__ unsigned fkey(float f) {
    unsigned u = __float_as_uint(f);
    return (u & 0x80000000u) ? ~u : (u | 0x80000000u);
}
__device__ __forceinline__ float fkey_inv(unsigned k) {
    return (k & 0x80000000u) ? __uint_as_float(k ^ 0x80000000u)
                             : __uint_as_float(~k);
}

// ---------------- kernels ---------------------------------------------------

// Detect index dtype: int64 little-endian has high word == 0 for every value
// (indices are in [0, 100000)). For int32 data the "high words" are random
// indices — all-zero over 128 samples is impossible in practice.
__global__ void k_detect(const int* __restrict__ ei_raw) {
    int all0 = 1;
    for (int i = 0; i < 128; i++)
        if (ei_raw[2 * i + 1] != 0) { all0 = 0; break; }
    g_is64 = all0;
}

__global__ void k_convert(const void* __restrict__ ei_raw,
                          const void* __restrict__ roots_raw) {
    int i = blockIdx.x * blockDim.x + threadIdx.x;
    int is64 = g_is64;
    if (i < N_EDGES) {
        if (is64) {
            const long long* e = (const long long*)ei_raw;
            g_src[i] = (int)e[i];
            g_dst[i] = (int)e[N_EDGES + i];
        } else {
            const int* e = (const int*)ei_raw;
            g_src[i] = e[i];
            g_dst[i] = e[N_EDGES + i];
        }
    }
    if (i < N_ROOTS) {
        g_root[i] = is64 ? (int)((const long long*)roots_raw)[i]
                         : ((const int*)roots_raw)[i];
    }
}

// h = x @ W + b ; s = lrelu(h.att_src) ; t = lrelu(h.att_dst)
// 64 rows per block staged in smem; 8 rows per warp in registers.
// Also zeroes acc / z / m for its rows (replaces the old k_init pass).
__global__ void __launch_bounds__(256) k_gemm(
        const float* __restrict__ x_ext, int use_x1,
        const float* __restrict__ W,  const float* __restrict__ b,
        const float* __restrict__ as_, const float* __restrict__ ad_) {
    __shared__ float sx[ROWS_PER_BLOCK][DIM];    // 32 KB

    const unsigned FULL = 0xffffffffu;
    int tid  = threadIdx.x;
    int wid  = tid >> 5;
    int lane = tid & 31;
    int row0 = blockIdx.x * ROWS_PER_BLOCK;

    const float4* x4 = (const float4*)(use_x1 ? g_x1 : x_ext);
    const float4* W4 = (const float4*)W;

    // stage 64 rows of x into smem (zero-fill out-of-range rows)
    for (int i = tid; i < ROWS_PER_BLOCK * 32; i += 256) {
        int r = i >> 5, c = i & 31;
        int row = row0 + r;
        float4 v = make_float4(0.f, 0.f, 0.f, 0.f);
        if (row < N_NODES) v = x4[row * 32 + c];
        ((float4*)sx[r])[c] = v;
    }
    __syncthreads();

    int rbase = wid * ROWS_PER_WARP;             // local row base for this warp
    float4 bias = ((const float4*)b)[lane];
    float4 acc[ROWS_PER_WARP];
    #pragma unroll
    for (int r = 0; r < ROWS_PER_WARP; r++) acc[r] = bias;

    #pragma unroll 2
    for (int kk = 0; kk < 32; kk++) {            // 4 k-values per iteration
        float4 w0 = W4[(4 * kk + 0) * 32 + lane];
        float4 w1 = W4[(4 * kk + 1) * 32 + lane];
        float4 w2 = W4[(4 * kk + 2) * 32 + lane];
        float4 w3 = W4[(4 * kk + 3) * 32 + lane];
        #pragma unroll
        for (int r = 0; r < ROWS_PER_WARP; r++) {
            float4 xv = ((const float4*)sx[rbase + r])[kk];  // broadcast LDS128
            acc[r].x += xv.x * w0.x; acc[r].y += xv.x * w0.y;
            acc[r].z += xv.x * w0.z; acc[r].w += xv.x * w0.w;
            acc[r].x += xv.y * w1.x; acc[r].y += xv.y * w1.y;
            acc[r].z += xv.y * w1.z; acc[r].w += xv.y * w1.w;
            acc[r].x += xv.z * w2.x; acc[r].y += xv.z * w2.y;
            acc[r].z += xv.z * w2.z; acc[r].w += xv.z * w2.w;
            acc[r].x += xv.w * w3.x; acc[r].y += xv.w * w3.y;
            acc[r].z += xv.w * w3.z; acc[r].w += xv.w * w3.w;
        }
    }

    float4 a4 = ((const float4*)as_)[lane];
    float4 d4 = ((const float4*)ad_)[lane];
    const float4 z4 = make_float4(0.f, 0.f, 0.f, 0.f);

    #pragma unroll
    for (int r = 0; r < ROWS_PER_WARP; r++) {
        int row = row0 + rbase + r;
        if (row >= N_NODES) break;
        ((float4*)g_h)[row * 32 + lane]   = acc[r];
        ((float4*)g_acc)[row * 32 + lane] = z4;      // zero accumulator

        float sp = acc[r].x * a4.x + acc[r].y * a4.y + acc[r].z * a4.z + acc[r].w * a4.w;
        float tp = acc[r].x * d4.x + acc[r].y * d4.y + acc[r].z * d4.z + acc[r].w * d4.w;
        #pragma unroll
        for (int o = 16; o; o >>= 1) {
            sp += __shfl_xor_sync(FULL, sp, o);
            tp += __shfl_xor_sync(FULL, tp, o);
        }
        if (lane == 0) {
            g_s[row] = sp > 0.f ? sp : NEG * sp;
            g_t[row] = tp > 0.f ? tp : NEG * tp;
            g_z[row] = 0.f;
            g_m[row] = 0u;
        }
    }
}

// per-edge scaled logit + segment max (atomicMax on encoded float)
__global__ void k_edge(const float* __restrict__ gu) {
    int i = blockIdx.x * blockDim.x + threadIdx.x;
    if (i >= N_EDGES) return;
    int s = g_src[i], d = g_dst[i];
    float u = gu[i];
    float g = -logf(-logf(u + EPS) + EPS);          // Gumbel(0,1)
    float l = (g_s[s] + g_t[d] + g) * TAU_INV;
    g_logit[i] = l;
    atomicMax(&g_m[d], fkey(l));
}

// one warp per edge: e = exp(l - m[dst]); z[dst] += e; acc[dst] += e * h[src]
__global__ void k_scatter() {
    int t = blockIdx.x * blockDim.x + threadIdx.x;
    int e = t >> 5;
    if (e >= N_EDGES) return;
    int lane = threadIdx.x & 31;
    const unsigned FULL = 0xffffffffu;

    int s = 0, d = 0; float w = 0.f;
    if (lane == 0) {
        s = g_src[e]; d = g_dst[e];
        float m = fkey_inv(g_m[d]);
        w = expf(g_logit[e] - m);
        atomicAdd(&g_z[d], w);
    }
    s = __shfl_sync(FULL, s, 0);
    d = __shfl_sync(FULL, d, 0);
    w = __shfl_sync(FULL, w, 0);

    float4 hv = ((const float4*)g_h)[s * 32 + lane];
    float* p = &g_acc[d * DIM + lane * 4];
    asm volatile("red.global.add.v4.f32 [%0], {%1,%2,%3,%4};"
                 :: "l"(p), "f"(w * hv.x), "f"(w * hv.y),
                    "f"(w * hv.z), "f"(w * hv.w) : "memory");
}

// hop-0 epilogue over all nodes: x1 = relu(acc/(z+eps) + x_in)
__global__ void k_finish(const float* __restrict__ x_ext) {
    int i = blockIdx.x * blockDim.x + threadIdx.x;
    if (i >= N_NODES * (DIM / 4)) return;
    int node = i >> 5;
    float inv = 1.f / (g_z[node] + EPS);
    float4 a = ((const float4*)g_acc)[i];
    float4 x = ((const float4*)x_ext)[i];
    float4 r;
    r.x = fmaxf(a.x * inv + x.x, 0.f);
    r.y = fmaxf(a.y * inv + x.y, 0.f);
    r.z = fmaxf(a.z * inv + x.z, 0.f);
    r.w = fmaxf(a.w * inv + x.w, 0.f);
    ((float4*)g_x1)[i] = r;
}

// hop-1 epilogue only at the 1024 roots, straight to d_out
__global__ void k_final(float* __restrict__ out) {
    int i = blockIdx.x * blockDim.x + threadIdx.x;
    if (i >= N_ROOTS * (DIM / 4)) return;
    int r = i >> 5, lane = i & 31;
    int node = g_root[r];
    float inv = 1.f / (g_z[node] + EPS);
    float4 a = ((const float4*)g_acc)[node * 32 + lane];
    float4 x = ((const float4*)g_x1)[node * 32 + lane];
    float4 o;
    o.x = fmaxf(a.x * inv + x.x, 0.f);
    o.y = fmaxf(a.y * inv + x.y, 0.f);
    o.z = fmaxf(a.z * inv + x.z, 0.f);
    o.w = fmaxf(a.w * inv + x.w, 0.f);
    ((float4*)out)[i] = o;
}

// ---------------- launch -----------------------------------------------------

extern "C" void kernel_launch(void* const* d_in, const int* in_sizes, int n_in,
                              void* d_out, int out_size) {
    const float* x     = (const float*)d_in[0];
    const void*  ei    = d_in[1];
    const void*  roots = d_in[2];
    const float* gu    = (const float*)d_in[3];
    const float* W     = (const float*)d_in[4];
    const float* b     = (const float*)d_in[5];
    const float* as_   = (const float*)d_in[6];
    const float* ad_   = (const float*)d_in[7];
    float*       out   = (float*)d_out;

    const int TB = 256;
    k_detect<<<1, 1>>>((const int*)ei);
    k_convert<<<(N_EDGES + TB - 1) / TB, TB>>>(ei, roots);

    int gemm_grid = (N_NODES + ROWS_PER_BLOCK - 1) / ROWS_PER_BLOCK;

    for (int hop = 0; hop < 2; hop++) {
        k_gemm<<<gemm_grid, 256>>>(x, hop, W, b, as_, ad_);
        k_edge<<<(N_EDGES + TB - 1) / TB, TB>>>(gu + (size_t)hop * N_EDGES);
        k_scatter<<<(N_EDGES * 32 + TB - 1) / TB, TB>>>();
        if (hop == 0) k_finish<<<(N_NODES * 32 + TB - 1) / TB, TB>>>(x);
        else          k_final<<<(N_ROOTS * 32 + TB - 1) / TB, TB>>>(out);
    }
}

// round 6
// speedup vs baseline: 2.7327x; 2.1619x over previous
#include <cuda_runtime.h>
#include <math.h>

#define N_NODES 100000
#define N_EDGES 1600000
#define DIM     128
#define N_ROOTS 1024
#define TAU_INV 10.0f
#define EPS     1e-10f
#define NEG     0.2f

#define ROWS_PER_BLOCK 64
#define ROWS_PER_WARP  8
#define SCAN_BLK 1024
#define SCAN_NBLK ((N_NODES + SCAN_BLK - 1) / SCAN_BLK)   // 98

// ---------------- scratch (device globals; no allocations allowed) ----------
__device__ __align__(16) float g_h  [N_NODES * DIM];   // h = xW + b
__device__ __align__(16) float g_x1 [N_NODES * DIM];   // hop-0 output
__device__ float g_s[N_NODES];
__device__ float g_t[N_NODES];
__device__ int   g_src [N_EDGES];
__device__ int   g_dst [N_EDGES];
__device__ int   g_srcs[N_EDGES];     // src sorted by dst (CSR payload)
__device__ int   g_perm[N_EDGES];     // original edge id in sorted order
__device__ int   g_deg [N_NODES];
__device__ int   g_off [N_NODES];     // CSR row start
__device__ int   g_cur [N_NODES];     // permute cursor
__device__ int   g_part[SCAN_NBLK + 1];
__device__ int   g_flag[N_NODES];
__device__ int   g_need[N_NODES];     // nodes needed for hop-1 gemm
__device__ int   g_need_cnt;
__device__ int   g_root[N_ROOTS];
__device__ int   g_is64;

// ---------------- preprocessing ---------------------------------------------

// int64 vs int32 index detection: int64 values < 100000 have zero high words.
__global__ void k_detect(const int* __restrict__ ei_raw) {
    int all0 = 1;
    for (int i = 0; i < 128; i++)
        if (ei_raw[2 * i + 1] != 0) { all0 = 0; break; }
    g_is64 = all0;
}

__global__ void k_convert(const void* __restrict__ ei_raw,
                          const void* __restrict__ roots_raw) {
    int i = blockIdx.x * blockDim.x + threadIdx.x;
    int is64 = g_is64;
    if (i < N_EDGES) {
        if (is64) {
            const long long* e = (const long long*)ei_raw;
            g_src[i] = (int)e[i];
            g_dst[i] = (int)e[N_EDGES + i];
        } else {
            const int* e = (const int*)ei_raw;
            g_src[i] = e[i];
            g_dst[i] = e[N_EDGES + i];
        }
    }
    if (i < N_ROOTS) {
        g_root[i] = is64 ? (int)((const long long*)roots_raw)[i]
                         : ((const int*)roots_raw)[i];
    }
    if (i < N_NODES) { g_deg[i] = 0; g_flag[i] = 0; }
    if (i == 0) g_need_cnt = 0;
}

__global__ void k_hist() {
    int i = blockIdx.x * blockDim.x + threadIdx.x;
    if (i < N_EDGES) atomicAdd(&g_deg[g_dst[i]], 1);
}

// two-level exclusive scan of g_deg -> g_off
__global__ void k_scanA() {
    __shared__ int sd[SCAN_BLK];
    int i = blockIdx.x * SCAN_BLK + threadIdx.x;
    int v = (i < N_NODES) ? g_deg[i] : 0;
    sd[threadIdx.x] = v;
    __syncthreads();
    for (int o = 1; o < SCAN_BLK; o <<= 1) {
        int t = (threadIdx.x >= o) ? sd[threadIdx.x - o] : 0;
        __syncthreads();
        sd[threadIdx.x] += t;
        __syncthreads();
    }
    if (i < N_NODES) g_off[i] = sd[threadIdx.x] - v;      // exclusive in block
    if (threadIdx.x == SCAN_BLK - 1) g_part[blockIdx.x] = sd[threadIdx.x];
}
__global__ void k_scanB() {
    int run = 0;
    for (int b = 0; b < SCAN_NBLK; b++) { int v = g_part[b]; g_part[b] = run; run += v; }
}
__global__ void k_scanC() {
    int i = blockIdx.x * blockDim.x + threadIdx.x;
    if (i >= N_NODES) return;
    int o = g_off[i] + g_part[i >> 10];
    g_off[i] = o;
    g_cur[i] = o;
}

__global__ void k_permute() {
    int i = blockIdx.x * blockDim.x + threadIdx.x;
    if (i >= N_EDGES) return;
    int d = g_dst[i];
    int pos = atomicAdd(&g_cur[d], 1);
    g_srcs[pos] = g_src[i];
    g_perm[pos] = i;
}

// mark nodes needed for hop-1 gemm: srcs of root-incident edges + roots
__global__ void k_markroots() {
    int w    = (blockIdx.x * blockDim.x + threadIdx.x) >> 5;
    int lane = threadIdx.x & 31;
    if (w >= N_ROOTS) return;
    int r   = g_root[w];
    int off = g_off[r], deg = g_deg[r];
    if (lane == 0) g_flag[r] = 1;
    for (int e = lane; e < deg; e += 32) g_flag[g_srcs[off + e]] = 1;
}
__global__ void k_compact() {
    int i = blockIdx.x * blockDim.x + threadIdx.x;
    if (i < N_NODES && g_flag[i]) g_need[atomicAdd(&g_need_cnt, 1)] = i;
}

// ---------------- gemm: h = x@W + b ; s,t = lrelu(h . att) -------------------
// 64 rows/block in smem, 8 rows/warp in registers.
// use_need=1: rows come indirected through g_need[0..g_need_cnt)
__global__ void __launch_bounds__(256) k_gemm(
        const float* __restrict__ x_ext, int use_x1, int use_need,
        const float* __restrict__ W,  const float* __restrict__ b,
        const float* __restrict__ as_, const float* __restrict__ ad_) {
    __shared__ float sx[ROWS_PER_BLOCK][DIM];
    __shared__ int   srow[ROWS_PER_BLOCK];

    const unsigned FULL = 0xffffffffu;
    int tid  = threadIdx.x;
    int wid  = tid >> 5;
    int lane = tid & 31;
    int row0 = blockIdx.x * ROWS_PER_BLOCK;
    int cnt  = use_need ? g_need_cnt : N_NODES;
    if (row0 >= cnt) return;

    const float4* x4 = (const float4*)(use_x1 ? g_x1 : x_ext);
    const float4* W4 = (const float4*)W;

    if (tid < ROWS_PER_BLOCK) {
        int gr = row0 + tid;
        srow[tid] = (gr < cnt) ? (use_need ? g_need[gr] : gr) : -1;
    }
    __syncthreads();

    for (int i = tid; i < ROWS_PER_BLOCK * 32; i += 256) {
        int r = i >> 5, c = i & 31;
        int node = srow[r];
        float4 v = make_float4(0.f, 0.f, 0.f, 0.f);
        if (node >= 0) v = x4[node * 32 + c];
        ((float4*)sx[r])[c] = v;
    }
    __syncthreads();

    int rbase = wid * ROWS_PER_WARP;
    float4 bias = ((const float4*)b)[lane];
    float4 acc[ROWS_PER_WARP];
    #pragma unroll
    for (int r = 0; r < ROWS_PER_WARP; r++) acc[r] = bias;

    #pragma unroll 2
    for (int kk = 0; kk < 32; kk++) {
        float4 w0 = W4[(4 * kk + 0) * 32 + lane];
        float4 w1 = W4[(4 * kk + 1) * 32 + lane];
        float4 w2 = W4[(4 * kk + 2) * 32 + lane];
        float4 w3 = W4[(4 * kk + 3) * 32 + lane];
        #pragma unroll
        for (int r = 0; r < ROWS_PER_WARP; r++) {
            float4 xv = ((const float4*)sx[rbase + r])[kk];
            acc[r].x += xv.x * w0.x; acc[r].y += xv.x * w0.y;
            acc[r].z += xv.x * w0.z; acc[r].w += xv.x * w0.w;
            acc[r].x += xv.y * w1.x; acc[r].y += xv.y * w1.y;
            acc[r].z += xv.y * w1.z; acc[r].w += xv.y * w1.w;
            acc[r].x += xv.z * w2.x; acc[r].y += xv.z * w2.y;
            acc[r].z += xv.z * w2.z; acc[r].w += xv.z * w2.w;
            acc[r].x += xv.w * w3.x; acc[r].y += xv.w * w3.y;
            acc[r].z += xv.w * w3.z; acc[r].w += xv.w * w3.w;
        }
    }

    float4 a4 = ((const float4*)as_)[lane];
    float4 d4 = ((const float4*)ad_)[lane];

    #pragma unroll
    for (int r = 0; r < ROWS_PER_WARP; r++) {
        int node = srow[rbase + r];
        if (node < 0) break;
        ((float4*)g_h)[node * 32 + lane] = acc[r];

        float sp = acc[r].x * a4.x + acc[r].y * a4.y + acc[r].z * a4.z + acc[r].w * a4.w;
        float tp = acc[r].x * d4.x + acc[r].y * d4.y + acc[r].z * d4.z + acc[r].w * d4.w;
        #pragma unroll
        for (int o = 16; o; o >>= 1) {
            sp += __shfl_xor_sync(FULL, sp, o);
            tp += __shfl_xor_sync(FULL, tp, o);
        }
        if (lane == 0) {
            g_s[node] = sp > 0.f ? sp : NEG * sp;
            g_t[node] = tp > 0.f ? tp : NEG * tp;
        }
    }
}

// ---------------- fused gather: online softmax + aggregate -------------------
// mode 0: one warp per node, residual = x_ext, write g_x1[node]
// mode 1: one warp per root, residual = g_x1,  write out[root_slot]
__device__ __forceinline__ void gather_body(
        int node, int lane, const float* __restrict__ gu,
        const float4* __restrict__ xprev4, float4* __restrict__ out4, int out_idx) {
    float t_n = g_t[node];
    int off = g_off[node], deg = g_deg[node];

    float m = -INFINITY, z = 0.f;
    float4 acc = make_float4(0.f, 0.f, 0.f, 0.f);

    for (int e = 0; e < deg; e++) {
        int srcn = g_srcs[off + e];
        int pe   = g_perm[off + e];
        float u  = gu[pe];
        float gn = -logf(-logf(u + EPS) + EPS);
        float l  = (g_s[srcn] + t_n + gn) * TAU_INV;
        if (l > m) {
            float c = expf(m - l);               // m=-inf -> 0: clean first iter
            z *= c; acc.x *= c; acc.y *= c; acc.z *= c; acc.w *= c;
            m = l;
        }
        float w = expf(l - m);
        z += w;
        float4 hv = ((const float4*)g_h)[srcn * 32 + lane];
        acc.x += w * hv.x; acc.y += w * hv.y;
        acc.z += w * hv.z; acc.w += w * hv.w;
    }

    float inv = 1.f / (z + EPS);                 // deg==0: acc==0 -> out=relu(x)
    float4 xp = xprev4[node * 32 + lane];
    float4 r;
    r.x = fmaxf(acc.x * inv + xp.x, 0.f);
    r.y = fmaxf(acc.y * inv + xp.y, 0.f);
    r.z = fmaxf(acc.z * inv + xp.z, 0.f);
    r.w = fmaxf(acc.w * inv + xp.w, 0.f);
    out4[out_idx * 32 + lane] = r;
}

__global__ void k_gather_all(const float* __restrict__ gu,
                             const float* __restrict__ x_ext) {
    int w    = (blockIdx.x * blockDim.x + threadIdx.x) >> 5;
    int lane = threadIdx.x & 31;
    if (w >= N_NODES) return;
    gather_body(w, lane, gu, (const float4*)x_ext, (float4*)g_x1, w);
}

__global__ void k_gather_roots(const float* __restrict__ gu,
                               float* __restrict__ out) {
    int w    = (blockIdx.x * blockDim.x + threadIdx.x) >> 5;
    int lane = threadIdx.x & 31;
    if (w >= N_ROOTS) return;
    gather_body(g_root[w], lane, gu, (const float4*)g_x1, (float4*)out, w);
}

// ---------------- launch -----------------------------------------------------

extern "C" void kernel_launch(void* const* d_in, const int* in_sizes, int n_in,
                              void* d_out, int out_size) {
    const float* x     = (const float*)d_in[0];
    const void*  ei    = d_in[1];
    const void*  roots = d_in[2];
    const float* gu    = (const float*)d_in[3];
    const float* W     = (const float*)d_in[4];
    const float* b     = (const float*)d_in[5];
    const float* as_   = (const float*)d_in[6];
    const float* ad_   = (const float*)d_in[7];
    float*       out   = (float*)d_out;

    const int TB = 256;
    const int EG = (N_EDGES + TB - 1) / TB;          // 6250
    const int NG = (N_NODES + TB - 1) / TB;          // 391

    k_detect <<<1, 1>>>((const int*)ei);
    k_convert<<<EG, TB>>>(ei, roots);
    k_hist   <<<EG, TB>>>();
    k_scanA  <<<SCAN_NBLK, SCAN_BLK>>>();
    k_scanB  <<<1, 1>>>();
    k_scanC  <<<NG, TB>>>();
    k_permute<<<EG, TB>>>();
    k_markroots<<<(N_ROOTS * 32 + TB - 1) / TB, TB>>>();
    k_compact<<<NG, TB>>>();

    int gemm_grid = (N_NODES + ROWS_PER_BLOCK - 1) / ROWS_PER_BLOCK;

    // hop 0: full graph
    k_gemm      <<<gemm_grid, 256>>>(x, 0, 0, W, b, as_, ad_);
    k_gather_all<<<(N_NODES * 32 + TB - 1) / TB, TB>>>(gu, x);

    // hop 1: only nodes feeding the roots
    k_gemm        <<<gemm_grid, 256>>>(x, 1, 1, W, b, as_, ad_);
    k_gather_roots<<<(N_ROOTS * 32 + TB - 1) / TB, TB>>>(gu + (size_t)N_EDGES, out);
}

// round 7
// speedup vs baseline: 3.5609x; 1.3031x over previous
#include <cuda_runtime.h>
#include <math.h>

#define N_NODES 100000
#define N_EDGES 1600000
#define DIM     128
#define N_ROOTS 1024
#define TAU_INV 10.0f
#define EPS     1e-10f
#define NEG     0.2f

#define ROWS_PER_BLOCK 64
#define ROWS_PER_WARP  8
#define SCAN_BLK 1024
#define SCAN_NBLK ((N_NODES + SCAN_BLK - 1) / SCAN_BLK)   // 98

// ---------------- scratch (device globals; no allocations allowed) ----------
__device__ __align__(16) float g_h  [N_NODES * DIM];   // h = xW + b
__device__ __align__(16) float g_x1 [N_NODES * DIM];   // hop-0 output
__device__ float g_s[N_NODES];
__device__ float g_t[N_NODES];
__device__ int   g_src [N_EDGES];
__device__ int   g_dst [N_EDGES];
__device__ __align__(8) int2 g_sp[N_EDGES];   // (src, orig-edge-id) sorted by dst
__device__ int   g_deg [N_NODES];
__device__ int   g_off [N_NODES];     // CSR row start
__device__ int   g_cur [N_NODES];     // permute cursor
__device__ int   g_part[SCAN_NBLK + 1];
__device__ int   g_flag[N_NODES];
__device__ int   g_need[N_NODES];     // nodes needed for hop-1 gemm
__device__ int   g_need_cnt;
__device__ int   g_root[N_ROOTS];
__device__ int   g_is64;

// ---------------- preprocessing ---------------------------------------------

// int64 vs int32 index detection: int64 values < 100000 have zero high words.
__global__ void k_detect(const int* __restrict__ ei_raw) {
    int all0 = 1;
    for (int i = 0; i < 128; i++)
        if (ei_raw[2 * i + 1] != 0) { all0 = 0; break; }
    g_is64 = all0;
}

__global__ void k_convert(const void* __restrict__ ei_raw,
                          const void* __restrict__ roots_raw) {
    int i = blockIdx.x * blockDim.x + threadIdx.x;
    int is64 = g_is64;
    if (i < N_EDGES) {
        if (is64) {
            const long long* e = (const long long*)ei_raw;
            g_src[i] = (int)e[i];
            g_dst[i] = (int)e[N_EDGES + i];
        } else {
            const int* e = (const int*)ei_raw;
            g_src[i] = e[i];
            g_dst[i] = e[N_EDGES + i];
        }
    }
    if (i < N_ROOTS) {
        g_root[i] = is64 ? (int)((const long long*)roots_raw)[i]
                         : ((const int*)roots_raw)[i];
    }
    if (i < N_NODES) { g_deg[i] = 0; g_flag[i] = 0; }
    if (i == 0) g_need_cnt = 0;
}

__global__ void k_hist() {
    int i = blockIdx.x * blockDim.x + threadIdx.x;
    if (i < N_EDGES) atomicAdd(&g_deg[g_dst[i]], 1);
}

// two-level exclusive scan of g_deg -> g_off
__global__ void k_scanA() {
    __shared__ int sd[SCAN_BLK];
    int i = blockIdx.x * SCAN_BLK + threadIdx.x;
    int v = (i < N_NODES) ? g_deg[i] : 0;
    sd[threadIdx.x] = v;
    __syncthreads();
    for (int o = 1; o < SCAN_BLK; o <<= 1) {
        int t = (threadIdx.x >= o) ? sd[threadIdx.x - o] : 0;
        __syncthreads();
        sd[threadIdx.x] += t;
        __syncthreads();
    }
    if (i < N_NODES) g_off[i] = sd[threadIdx.x] - v;      // exclusive in block
    if (threadIdx.x == SCAN_BLK - 1) g_part[blockIdx.x] = sd[threadIdx.x];
}
__global__ void k_scanB() {
    int run = 0;
    for (int b = 0; b < SCAN_NBLK; b++) { int v = g_part[b]; g_part[b] = run; run += v; }
}
__global__ void k_scanC() {
    int i = blockIdx.x * blockDim.x + threadIdx.x;
    if (i >= N_NODES) return;
    int o = g_off[i] + g_part[i >> 10];
    g_off[i] = o;
    g_cur[i] = o;
}

__global__ void k_permute() {
    int i = blockIdx.x * blockDim.x + threadIdx.x;
    if (i >= N_EDGES) return;
    int d = g_dst[i];
    int pos = atomicAdd(&g_cur[d], 1);
    g_sp[pos] = make_int2(g_src[i], i);
}

// mark nodes needed for hop-1 gemm: srcs of root-incident edges + roots
__global__ void k_markroots() {
    int w    = (blockIdx.x * blockDim.x + threadIdx.x) >> 5;
    int lane = threadIdx.x & 31;
    if (w >= N_ROOTS) return;
    int r   = g_root[w];
    int off = g_off[r], deg = g_deg[r];
    if (lane == 0) g_flag[r] = 1;
    for (int e = lane; e < deg; e += 32) g_flag[g_sp[off + e].x] = 1;
}
__global__ void k_compact() {
    int i = blockIdx.x * blockDim.x + threadIdx.x;
    if (i < N_NODES && g_flag[i]) g_need[atomicAdd(&g_need_cnt, 1)] = i;
}

// ---------------- gemm: h = x@W + b ; s,t = lrelu(h . att) -------------------
__global__ void __launch_bounds__(256) k_gemm(
        const float* __restrict__ x_ext, int use_x1, int use_need,
        const float* __restrict__ W,  const float* __restrict__ b,
        const float* __restrict__ as_, const float* __restrict__ ad_) {
    __shared__ float sx[ROWS_PER_BLOCK][DIM];
    __shared__ int   srow[ROWS_PER_BLOCK];

    const unsigned FULL = 0xffffffffu;
    int tid  = threadIdx.x;
    int wid  = tid >> 5;
    int lane = tid & 31;
    int row0 = blockIdx.x * ROWS_PER_BLOCK;
    int cnt  = use_need ? g_need_cnt : N_NODES;
    if (row0 >= cnt) return;

    const float4* x4 = (const float4*)(use_x1 ? g_x1 : x_ext);
    const float4* W4 = (const float4*)W;

    if (tid < ROWS_PER_BLOCK) {
        int gr = row0 + tid;
        srow[tid] = (gr < cnt) ? (use_need ? g_need[gr] : gr) : -1;
    }
    __syncthreads();

    for (int i = tid; i < ROWS_PER_BLOCK * 32; i += 256) {
        int r = i >> 5, c = i & 31;
        int node = srow[r];
        float4 v = make_float4(0.f, 0.f, 0.f, 0.f);
        if (node >= 0) v = x4[node * 32 + c];
        ((float4*)sx[r])[c] = v;
    }
    __syncthreads();

    int rbase = wid * ROWS_PER_WARP;
    float4 bias = ((const float4*)b)[lane];
    float4 acc[ROWS_PER_WARP];
    #pragma unroll
    for (int r = 0; r < ROWS_PER_WARP; r++) acc[r] = bias;

    #pragma unroll 2
    for (int kk = 0; kk < 32; kk++) {
        float4 w0 = W4[(4 * kk + 0) * 32 + lane];
        float4 w1 = W4[(4 * kk + 1) * 32 + lane];
        float4 w2 = W4[(4 * kk + 2) * 32 + lane];
        float4 w3 = W4[(4 * kk + 3) * 32 + lane];
        #pragma unroll
        for (int r = 0; r < ROWS_PER_WARP; r++) {
            float4 xv = ((const float4*)sx[rbase + r])[kk];
            acc[r].x += xv.x * w0.x; acc[r].y += xv.x * w0.y;
            acc[r].z += xv.x * w0.z; acc[r].w += xv.x * w0.w;
            acc[r].x += xv.y * w1.x; acc[r].y += xv.y * w1.y;
            acc[r].z += xv.y * w1.z; acc[r].w += xv.y * w1.w;
            acc[r].x += xv.z * w2.x; acc[r].y += xv.z * w2.y;
            acc[r].z += xv.z * w2.z; acc[r].w += xv.z * w2.w;
            acc[r].x += xv.w * w3.x; acc[r].y += xv.w * w3.y;
            acc[r].z += xv.w * w3.z; acc[r].w += xv.w * w3.w;
        }
    }

    float4 a4 = ((const float4*)as_)[lane];
    float4 d4 = ((const float4*)ad_)[lane];

    #pragma unroll
    for (int r = 0; r < ROWS_PER_WARP; r++) {
        int node = srow[rbase + r];
        if (node < 0) break;
        ((float4*)g_h)[node * 32 + lane] = acc[r];

        float sp = acc[r].x * a4.x + acc[r].y * a4.y + acc[r].z * a4.z + acc[r].w * a4.w;
        float tp = acc[r].x * d4.x + acc[r].y * d4.y + acc[r].z * d4.z + acc[r].w * d4.w;
        #pragma unroll
        for (int o = 16; o; o >>= 1) {
            sp += __shfl_xor_sync(FULL, sp, o);
            tp += __shfl_xor_sync(FULL, tp, o);
        }
        if (lane == 0) {
            g_s[node] = sp > 0.f ? sp : NEG * sp;
            g_t[node] = tp > 0.f ? tp : NEG * tp;
        }
    }
}

// ---------------- fused gather: lane-parallel online softmax -----------------
// One warp per output node. Per 32-edge chunk: each lane computes ONE edge's
// logit (accurate logf), warp-reduce max, uniform rescale, per-lane __expf
// weight, warp-reduce z; then a serial shfl+LDG.128 loop accumulates w*h[src].
__device__ __forceinline__ void gather_body(
        int node, int lane, const float* __restrict__ gu,
        const float4* __restrict__ xprev4, float4* __restrict__ out4, int out_idx) {
    const unsigned FULL = 0xffffffffu;
    float t_n = g_t[node];
    int off = g_off[node], deg = g_deg[node];

    float m = -INFINITY, z = 0.f;
    float4 acc = make_float4(0.f, 0.f, 0.f, 0.f);

    for (int base = 0; base < deg; base += 32) {
        int n_chunk = min(32, deg - base);
        int e = base + lane;
        float l = -INFINITY;
        int srcn = 0;
        if (e < deg) {
            int2 sp = g_sp[off + e];
            srcn = sp.x;
            float u  = gu[sp.y];
            float gn = -logf(-logf(u + EPS) + EPS);
            l = (g_s[srcn] + t_n + gn) * TAU_INV;
        }
        // warp max of this chunk's logits
        float cm = l;
        #pragma unroll
        for (int o = 16; o; o >>= 1) cm = fmaxf(cm, __shfl_xor_sync(FULL, cm, o));
        if (cm > m) {
            float c = __expf(m - cm);            // m=-inf on first chunk -> 0
            z *= c; acc.x *= c; acc.y *= c; acc.z *= c; acc.w *= c;
            m = cm;
        }
        float w = (e < deg) ? __expf(l - m) : 0.f;
        float ws = w;
        #pragma unroll
        for (int o = 16; o; o >>= 1) ws += __shfl_xor_sync(FULL, ws, o);
        z += ws;

        // serial accumulation of w_j * h[src_j][lane slice]
        for (int j = 0; j < n_chunk; j++) {
            float wj = __shfl_sync(FULL, w, j);
            int   sj = __shfl_sync(FULL, srcn, j);
            float4 hv = ((const float4*)g_h)[sj * 32 + lane];
            acc.x += wj * hv.x; acc.y += wj * hv.y;
            acc.z += wj * hv.z; acc.w += wj * hv.w;
        }
    }

    float inv = 1.f / (z + EPS);                 // deg==0: acc==0 -> out=relu(x)
    float4 xp = xprev4[node * 32 + lane];
    float4 r;
    r.x = fmaxf(acc.x * inv + xp.x, 0.f);
    r.y = fmaxf(acc.y * inv + xp.y, 0.f);
    r.z = fmaxf(acc.z * inv + xp.z, 0.f);
    r.w = fmaxf(acc.w * inv + xp.w, 0.f);
    out4[out_idx * 32 + lane] = r;
}

__global__ void k_gather_all(const float* __restrict__ gu,
                             const float* __restrict__ x_ext) {
    int w    = (blockIdx.x * blockDim.x + threadIdx.x) >> 5;
    int lane = threadIdx.x & 31;
    if (w >= N_NODES) return;
    gather_body(w, lane, gu, (const float4*)x_ext, (float4*)g_x1, w);
}

__global__ void k_gather_roots(const float* __restrict__ gu,
                               float* __restrict__ out) {
    int w    = (blockIdx.x * blockDim.x + threadIdx.x) >> 5;
    int lane = threadIdx.x & 31;
    if (w >= N_ROOTS) return;
    gather_body(g_root[w], lane, gu, (const float4*)g_x1, (float4*)out, w);
}

// ---------------- launch -----------------------------------------------------

extern "C" void kernel_launch(void* const* d_in, const int* in_sizes, int n_in,
                              void* d_out, int out_size) {
    const float* x     = (const float*)d_in[0];
    const void*  ei    = d_in[1];
    const void*  roots = d_in[2];
    const float* gu    = (const float*)d_in[3];
    const float* W     = (const float*)d_in[4];
    const float* b     = (const float*)d_in[5];
    const float* as_   = (const float*)d_in[6];
    const float* ad_   = (const float*)d_in[7];
    float*       out   = (float*)d_out;

    const int TB = 256;
    const int EG = (N_EDGES + TB - 1) / TB;          // 6250
    const int NG = (N_NODES + TB - 1) / TB;          // 391

    k_detect <<<1, 1>>>((const int*)ei);
    k_convert<<<EG, TB>>>(ei, roots);
    k_hist   <<<EG, TB>>>();
    k_scanA  <<<SCAN_NBLK, SCAN_BLK>>>();
    k_scanB  <<<1, 1>>>();
    k_scanC  <<<NG, TB>>>();
    k_permute<<<EG, TB>>>();
    k_markroots<<<(N_ROOTS * 32 + TB - 1) / TB, TB>>>();
    k_compact<<<NG, TB>>>();

    int gemm_grid = (N_NODES + ROWS_PER_BLOCK - 1) / ROWS_PER_BLOCK;

    // hop 0: full graph
    k_gemm      <<<gemm_grid, 256>>>(x, 0, 0, W, b, as_, ad_);
    k_gather_all<<<(N_NODES * 32 + TB - 1) / TB, TB>>>(gu, x);

    // hop 1: only nodes feeding the roots
    k_gemm        <<<gemm_grid, 256>>>(x, 1, 1, W, b, as_, ad_);
    k_gather_roots<<<(N_ROOTS * 32 + TB - 1) / TB, TB>>>(gu + (size_t)N_EDGES, out);
}

// round 9
// speedup vs baseline: 3.7766x; 1.0606x over previous
#include <cuda_runtime.h>
#include <math.h>

#define N_NODES 100000
#define N_EDGES 1600000
#define DIM     128
#define N_ROOTS 1024
#define TAU_INV 10.0f
#define EPS     1e-10f
#define NEG     0.2f

#define ROWS_PER_BLOCK 64
#define ROWS_PER_WARP  8
#define SCAN_BLK 1024
#define SCAN_NBLK ((N_NODES + SCAN_BLK - 1) / SCAN_BLK)   // 98

typedef unsigned long long u64;

// ---------------- scratch (device globals; no allocations allowed) ----------
__device__ __align__(16) float g_h  [N_NODES * DIM];   // h = xW + b
__device__ __align__(16) float g_x1 [N_NODES * DIM];   // hop-0 output
__device__ float g_s[N_NODES];
__device__ float g_t[N_NODES];
__device__ int   g_src [N_EDGES];
__device__ int   g_dst [N_EDGES];
__device__ __align__(8) int2 g_sp[N_EDGES];   // (src, orig-edge-id) sorted by dst
__device__ int   g_deg [N_NODES];
__device__ int   g_off [N_NODES];
__device__ int   g_cur [N_NODES];
__device__ int   g_part[SCAN_NBLK + 1];
__device__ int   g_flag[N_NODES];
__device__ int   g_need[N_NODES];
__device__ int   g_need_cnt;
__device__ int   g_root[N_ROOTS];
__device__ int   g_is64;

// ---------------- f32x2 packed-FFMA helpers ---------------------------------
__device__ __forceinline__ u64 pack2(float a, float b) {
    u64 r; asm("mov.b64 %0, {%1, %2};" : "=l"(r) : "f"(a), "f"(b)); return r;
}
__device__ __forceinline__ u64 dup2(float a) {
    u64 r; asm("mov.b64 %0, {%1, %1};" : "=l"(r) : "f"(a)); return r;
}
__device__ __forceinline__ void fma2(u64& d, u64 a, u64 b) {
    asm("fma.rn.f32x2 %0, %1, %2, %3;" : "=l"(d) : "l"(a), "l"(b), "l"(d));
}
__device__ __forceinline__ float2 unpk2(u64 v) {
    float2 f; asm("mov.b64 {%0, %1}, %2;" : "=f"(f.x), "=f"(f.y) : "l"(v)); return f;
}

// ---------------- preprocessing ---------------------------------------------

// int64 vs int32 detection, parallel: int64 values < 100000 have 0 high words.
__global__ void k_detect(const int* __restrict__ ei_raw) {
    __shared__ int ok;
    if (threadIdx.x == 0) ok = 1;
    __syncthreads();
    if (ei_raw[2 * threadIdx.x + 1] != 0) ok = 0;   // benign race
    __syncthreads();
    if (threadIdx.x == 0) g_is64 = ok;
}

__global__ void k_zero() {
    int i = blockIdx.x * blockDim.x + threadIdx.x;
    if (i < N_NODES) { g_deg[i] = 0; g_flag[i] = 0; }
    if (i == 0) g_need_cnt = 0;
}

// convert indices AND build the dst histogram in one pass
__global__ void k_convert(const void* __restrict__ ei_raw,
                          const void* __restrict__ roots_raw) {
    int i = blockIdx.x * blockDim.x + threadIdx.x;
    int is64 = g_is64;
    if (i < N_EDGES) {
        int s, d;
        if (is64) {
            const long long* e = (const long long*)ei_raw;
            s = (int)e[i]; d = (int)e[N_EDGES + i];
        } else {
            const int* e = (const int*)ei_raw;
            s = e[i]; d = e[N_EDGES + i];
        }
        g_src[i] = s; g_dst[i] = d;
        atomicAdd(&g_deg[d], 1);
    }
    if (i < N_ROOTS) {
        g_root[i] = is64 ? (int)((const long long*)roots_raw)[i]
                         : ((const int*)roots_raw)[i];
    }
}

// two-level exclusive scan of g_deg -> g_off
__global__ void k_scanA() {
    __shared__ int sd[SCAN_BLK];
    int i = blockIdx.x * SCAN_BLK + threadIdx.x;
    int v = (i < N_NODES) ? g_deg[i] : 0;
    sd[threadIdx.x] = v;
    __syncthreads();
    for (int o = 1; o < SCAN_BLK; o <<= 1) {
        int t = (threadIdx.x >= o) ? sd[threadIdx.x - o] : 0;
        __syncthreads();
        sd[threadIdx.x] += t;
        __syncthreads();
    }
    if (i < N_NODES) g_off[i] = sd[threadIdx.x] - v;
    if (threadIdx.x == SCAN_BLK - 1) g_part[blockIdx.x] = sd[threadIdx.x];
}
__global__ void k_scanB() {
    int run = 0;
    for (int b = 0; b < SCAN_NBLK; b++) { int v = g_part[b]; g_part[b] = run; run += v; }
}
__global__ void k_scanC() {
    int i = blockIdx.x * blockDim.x + threadIdx.x;
    if (i >= N_NODES) return;
    int o = g_off[i] + g_part[i >> 10];
    g_off[i] = o;
    g_cur[i] = o;
}

__global__ void k_permute() {
    int i = blockIdx.x * blockDim.x + threadIdx.x;
    if (i >= N_EDGES) return;
    int d = g_dst[i];
    int pos = atomicAdd(&g_cur[d], 1);
    g_sp[pos] = make_int2(g_src[i], i);
}

// mark nodes needed for hop-1 gemm: srcs of root-incident edges + roots
__global__ void k_markroots() {
    int w    = (blockIdx.x * blockDim.x + threadIdx.x) >> 5;
    int lane = threadIdx.x & 31;
    if (w >= N_ROOTS) return;
    int r   = g_root[w];
    int off = g_off[r], deg = g_deg[r];
    if (lane == 0) g_flag[r] = 1;
    for (int e = lane; e < deg; e += 32) g_flag[g_sp[off + e].x] = 1;
}
__global__ void k_compact() {
    int i = blockIdx.x * blockDim.x + threadIdx.x;
    if (i < N_NODES && g_flag[i]) g_need[atomicAdd(&g_need_cnt, 1)] = i;
}

// ---------------- gemm: h = x@W + b ; s,t = lrelu(h . att) -------------------
// 64 rows/block in smem, 8 rows/warp. Inner product via packed fma.rn.f32x2:
// W cols pair naturally into 64-bit halves; x scalar duplicated per k.
__global__ void __launch_bounds__(256) k_gemm(
        const float* __restrict__ x_ext, int use_x1, int use_need,
        const float* __restrict__ W,  const float* __restrict__ b,
        const float* __restrict__ as_, const float* __restrict__ ad_) {
    __shared__ float sx[ROWS_PER_BLOCK][DIM];
    __shared__ int   srow[ROWS_PER_BLOCK];

    const unsigned FULL = 0xffffffffu;
    int tid  = threadIdx.x;
    int wid  = tid >> 5;
    int lane = tid & 31;
    int row0 = blockIdx.x * ROWS_PER_BLOCK;
    int cnt  = use_need ? g_need_cnt : N_NODES;
    if (row0 >= cnt) return;

    const float4* x4 = (const float4*)(use_x1 ? g_x1 : x_ext);
    const ulonglong2* W2 = (const ulonglong2*)W;   // [row][lane] -> cols(4l..4l+3)

    if (tid < ROWS_PER_BLOCK) {
        int gr = row0 + tid;
        srow[tid] = (gr < cnt) ? (use_need ? g_need[gr] : gr) : -1;
    }
    __syncthreads();

    for (int i = tid; i < ROWS_PER_BLOCK * 32; i += 256) {
        int r = i >> 5, c = i & 31;
        int node = srow[r];
        float4 v = make_float4(0.f, 0.f, 0.f, 0.f);
        if (node >= 0) v = x4[node * 32 + c];
        ((float4*)sx[r])[c] = v;
    }
    __syncthreads();

    int rbase = wid * ROWS_PER_WARP;
    float4 bias = ((const float4*)b)[lane];
    u64 acc2[ROWS_PER_WARP][2];
    #pragma unroll
    for (int r = 0; r < ROWS_PER_WARP; r++) {
        acc2[r][0] = pack2(bias.x, bias.y);
        acc2[r][1] = pack2(bias.z, bias.w);
    }

    #pragma unroll 2
    for (int kk = 0; kk < 32; kk++) {
        ulonglong2 w0 = W2[(4 * kk + 0) * 32 + lane];   // .x = cols(4l,4l+1)
        ulonglong2 w1 = W2[(4 * kk + 1) * 32 + lane];
        ulonglong2 w2 = W2[(4 * kk + 2) * 32 + lane];
        ulonglong2 w3 = W2[(4 * kk + 3) * 32 + lane];
        #pragma unroll
        for (int r = 0; r < ROWS_PER_WARP; r++) {
            float4 xv = ((const float4*)sx[rbase + r])[kk];
            u64 x0 = dup2(xv.x), x1 = dup2(xv.y), x2 = dup2(xv.z), x3 = dup2(xv.w);
            fma2(acc2[r][0], x0, w0.x); fma2(acc2[r][1], x0, w0.y);
            fma2(acc2[r][0], x1, w1.x); fma2(acc2[r][1], x1, w1.y);
            fma2(acc2[r][0], x2, w2.x); fma2(acc2[r][1], x2, w2.y);
            fma2(acc2[r][0], x3, w3.x); fma2(acc2[r][1], x3, w3.y);
        }
    }

    float4 a4 = ((const float4*)as_)[lane];
    float4 d4 = ((const float4*)ad_)[lane];

    #pragma unroll
    for (int r = 0; r < ROWS_PER_WARP; r++) {
        int node = srow[rbase + r];
        if (node < 0) break;
        float2 lo = unpk2(acc2[r][0]), hi = unpk2(acc2[r][1]);
        float4 acc = make_float4(lo.x, lo.y, hi.x, hi.y);
        ((float4*)g_h)[node * 32 + lane] = acc;

        float sp = acc.x * a4.x + acc.y * a4.y + acc.z * a4.z + acc.w * a4.w;
        float tp = acc.x * d4.x + acc.y * d4.y + acc.z * d4.z + acc.w * d4.w;
        #pragma unroll
        for (int o = 16; o; o >>= 1) {
            sp += __shfl_xor_sync(FULL, sp, o);
            tp += __shfl_xor_sync(FULL, tp, o);
        }
        if (lane == 0) {
            g_s[node] = sp > 0.f ? sp : NEG * sp;
            g_t[node] = tp > 0.f ? tp : NEG * tp;
        }
    }
}

// ---------------- fused gather: lane-parallel online softmax -----------------
// Per 32-edge chunk: lane-parallel logits (accurate logf), warp max, per-lane
// __expf weights staged to per-warp smem as (w, src) pairs; then an unrolled
// LDS.64 + LDG.128 accumulation loop (z folded in — no separate reduction).
__device__ __forceinline__ void gather_body(
        int node, int lane, int wslot, float2* __restrict__ s_we,
        const float* __restrict__ gu,
        const float4* __restrict__ xprev4, float4* __restrict__ out4, int out_idx) {
    const unsigned FULL = 0xffffffffu;
    float t_n = g_t[node];
    int off = g_off[node], deg = g_deg[node];

    float m = -INFINITY, z = 0.f;
    float4 acc = make_float4(0.f, 0.f, 0.f, 0.f);

    for (int base = 0; base < deg; base += 32) {
        int n_chunk = min(32, deg - base);
        int e = base + lane;
        float l = -INFINITY;
        int srcn = 0;
        if (e < deg) {
            int2 sp = g_sp[off + e];
            srcn = sp.x;
            float u  = gu[sp.y];
            float gn = -logf(-logf(u + EPS) + EPS);
            l = (g_s[srcn] + t_n + gn) * TAU_INV;
        }
        float cm = l;
        #pragma unroll
        for (int o = 16; o; o >>= 1) cm = fmaxf(cm, __shfl_xor_sync(FULL, cm, o));
        if (cm > m) {
            float c = __expf(m - cm);            // m=-inf on first chunk -> 0
            z *= c; acc.x *= c; acc.y *= c; acc.z *= c; acc.w *= c;
            m = cm;
        }
        float w = (e < deg) ? __expf(l - m) : 0.f;
        s_we[wslot * 32 + lane] = make_float2(w, __int_as_float(srcn));
        __syncwarp();

        #pragma unroll 4
        for (int j = 0; j < n_chunk; j++) {
            float2 we = s_we[wslot * 32 + j];    // broadcast LDS.64
            float wj = we.x;
            int   sj = __float_as_int(we.y);
            float4 hv = ((const float4*)g_h)[sj * 32 + lane];
            z += wj;                             // identical in all lanes
            acc.x += wj * hv.x; acc.y += wj * hv.y;
            acc.z += wj * hv.z; acc.w += wj * hv.w;
        }
        __syncwarp();
    }

    float inv = 1.f / (z + EPS);                 // deg==0 -> out = relu(x)
    float4 xp = xprev4[node * 32 + lane];
    float4 r;
    r.x = fmaxf(acc.x * inv + xp.x, 0.f);
    r.y = fmaxf(acc.y * inv + xp.y, 0.f);
    r.z = fmaxf(acc.z * inv + xp.z, 0.f);
    r.w = fmaxf(acc.w * inv + xp.w, 0.f);
    out4[out_idx * 32 + lane] = r;
}

__global__ void __launch_bounds__(256) k_gather_all(
        const float* __restrict__ gu, const float* __restrict__ x_ext) {
    __shared__ float2 s_we[8 * 32];
    int w    = (blockIdx.x * blockDim.x + threadIdx.x) >> 5;
    int lane = threadIdx.x & 31;
    if (w >= N_NODES) return;
    gather_body(w, lane, threadIdx.x >> 5, s_we, gu,
                (const float4*)x_ext, (float4*)g_x1, w);
}

__global__ void __launch_bounds__(256) k_gather_roots(
        const float* __restrict__ gu, float* __restrict__ out) {
    __shared__ float2 s_we[8 * 32];
    int w    = (blockIdx.x * blockDim.x + threadIdx.x) >> 5;
    int lane = threadIdx.x & 31;
    if (w >= N_ROOTS) return;
    gather_body(g_root[w], lane, threadIdx.x >> 5, s_we, gu,
                (const float4*)g_x1, (float4*)out, w);
}

// ---------------- launch -----------------------------------------------------

extern "C" void kernel_launch(void* const* d_in, const int* in_sizes, int n_in,
                              void* d_out, int out_size) {
    const float* x     = (const float*)d_in[0];
    const void*  ei    = d_in[1];
    const void*  roots = d_in[2];
    const float* gu    = (const float*)d_in[3];
    const float* W     = (const float*)d_in[4];
    const float* b     = (const float*)d_in[5];
    const float* as_   = (const float*)d_in[6];
    const float* ad_   = (const float*)d_in[7];
    float*       out   = (float*)d_out;

    const int TB = 256;
    const int EG = (N_EDGES + TB - 1) / TB;          // 6250
    const int NG = (N_NODES + TB - 1) / TB;          // 391

    k_detect <<<1, 128>>>((const int*)ei);
    k_zero   <<<NG, TB>>>();
    k_convert<<<EG, TB>>>(ei, roots);
    k_scanA  <<<SCAN_NBLK, SCAN_BLK>>>();
    k_scanB  <<<1, 1>>>();
    k_scanC  <<<NG, TB>>>();
    k_permute<<<EG, TB>>>();
    k_markroots<<<(N_ROOTS * 32 + TB - 1) / TB, TB>>>();
    k_compact<<<NG, TB>>>();

    int gemm_grid = (N_NODES + ROWS_PER_BLOCK - 1) / ROWS_PER_BLOCK;

    // hop 0: full graph
    k_gemm      <<<gemm_grid, 256>>>(x, 0, 0, W, b, as_, ad_);
    k_gather_all<<<(N_NODES * 32 + TB - 1) / TB, TB>>>(gu, x);

    // hop 1: only nodes feeding the roots
    k_gemm        <<<gemm_grid, 256>>>(x, 1, 1, W, b, as_, ad_);
    k_gather_roots<<<(N_ROOTS * 32 + TB - 1) / TB, TB>>>(gu + (size_t)N_EDGES, out);
}